// round 4
// baseline (speedup 1.0000x reference)
#include <cuda_runtime.h>
#include <cuda_bf16.h>

#define NMAX   100352        // >= N=100000
#define CUT2   0.81f         // 0.9^2
#define PREFAC 138.93544539709032f

// Static device scratch (allocation-free rule).
__device__ float4 g_pos[NMAX];       // x, y, z, charge
__device__ float2 g_par[NMAX];       // sigma, sqrt(eps)
__device__ double g_acc;
__device__ unsigned int g_done;

// ---------------------------------------------------------------------------
// Pack: build 16B gather records; reset accumulator + done counter.
// ---------------------------------------------------------------------------
__global__ void nb_pack_kernel(const float* __restrict__ coords,
                               const float* __restrict__ charges,
                               const float* __restrict__ sigma,
                               const float* __restrict__ epsilon,
                               int n)
{
    int i = blockIdx.x * blockDim.x + threadIdx.x;
    if (i == 0) { g_acc = 0.0; g_done = 0u; }
    if (i < n) {
        g_pos[i] = make_float4(coords[3 * i + 0],
                               coords[3 * i + 1],
                               coords[3 * i + 2],
                               charges[i]);
        g_par[i] = make_float2(sigma[i], sqrtf(epsilon[i]));
    }
}

// ---------------------------------------------------------------------------
// Min-image r^2: for |d| < L, (d - L*round(d/L))^2 == min(|d|, L-|d|)^2.
// Compiles to 3x{FADD, FADD(abs-src), FMNMX(abs-src)} + FMUL + 2 FFMA.
// ---------------------------------------------------------------------------
__device__ __forceinline__ float min_image_r2(const float4 a, const float4 b,
                                              float Lx, float Ly, float Lz)
{
    float dx = fabsf(a.x - b.x); dx = fminf(dx, Lx - dx);
    float dy = fabsf(a.y - b.y); dy = fminf(dy, Ly - dy);
    float dz = fabsf(a.z - b.z); dz = fminf(dz, Lz - dz);
    return fmaf(dx, dx, fmaf(dy, dy, dz * dz));
}

// ---------------------------------------------------------------------------
// Rare path (~0.3% of pairs): full Coulomb + LJ, molecule exclusion by index.
// ---------------------------------------------------------------------------
__device__ __forceinline__ float pair_energy(int i, int j,
                                             float qi, float qj, float r2)
{
    if (i / 3 == j / 3) return 0.0f;     // same molecule (covers i == j)

    float2 pa = __ldg(&g_par[i]);
    float2 pb = __ldg(&g_par[j]);

    float inv_r = rsqrtf(r2);
    inv_r = inv_r * fmaf(-0.5f * r2 * inv_r, inv_r, 1.5f);   // Newton step

    float e_coul = PREFAC * qi * qj * inv_r;

    float sig  = 0.5f * (pa.x + pb.x);
    float eps  = pa.y * pb.y;            // sqrt(ei)*sqrt(ej)
    float ir2  = inv_r * inv_r;
    float sr2  = sig * sig * ir2;
    float sr6  = sr2 * sr2 * sr2;
    float e_lj = 4.0f * eps * (sr6 * sr6 - sr6);

    return e_coul + e_lj;
}

// ---------------------------------------------------------------------------
// Main: grid-stride over int4 units (2 pairs/unit), unrolled x2 (4 pairs,
// 8 gathers batched per iteration). Last block writes the float result.
// ---------------------------------------------------------------------------
__global__ __launch_bounds__(256)
void nb_pair_kernel(const int4* __restrict__ pairs4,
                    long long nUnits,
                    int nPairs,
                    const float* __restrict__ box,
                    float* __restrict__ out)
{
    const float Lx = __ldg(&box[0]);
    const float Ly = __ldg(&box[4]);
    const float Lz = __ldg(&box[8]);

    double acc = 0.0;

    const long long stride = (long long)gridDim.x * blockDim.x;
    for (long long u = (long long)blockIdx.x * blockDim.x + threadIdx.x;
         u < nUnits; u += 2 * stride)
    {
        const long long u2   = u + stride;
        const bool      hasB = (u2 < nUnits);

        const int4 pA = __ldg(&pairs4[u]);
        const int4 pB = hasB ? __ldg(&pairs4[u2]) : pA;

        // Batch all 8 gathers up front (front-loaded MLP for the L1tex queue).
        const float4 a0 = __ldg(&g_pos[pA.x]);
        const float4 b0 = __ldg(&g_pos[pA.y]);
        const float4 a1 = __ldg(&g_pos[pA.z]);
        const float4 b1 = __ldg(&g_pos[pA.w]);
        const float4 c0 = __ldg(&g_pos[pB.x]);
        const float4 d0 = __ldg(&g_pos[pB.y]);
        const float4 c1 = __ldg(&g_pos[pB.z]);
        const float4 d1 = __ldg(&g_pos[pB.w]);

        const float r2a = min_image_r2(a0, b0, Lx, Ly, Lz);
        const float r2b = min_image_r2(a1, b1, Lx, Ly, Lz);
        const float r2c = min_image_r2(c0, d0, Lx, Ly, Lz);
        const float r2d = min_image_r2(c1, d1, Lx, Ly, Lz);

        const bool va = (r2a < CUT2);
        const bool vb = (r2b < CUT2);
        const bool vc = (r2c < CUT2) && hasB;
        const bool vd = (r2d < CUT2) && hasB;

        if (va | vb | vc | vd) {         // rare
            if (va) acc += (double)pair_energy(pA.x, pA.y, a0.w, b0.w, r2a);
            if (vb) acc += (double)pair_energy(pA.z, pA.w, a1.w, b1.w, r2b);
            if (vc) acc += (double)pair_energy(pB.x, pB.y, c0.w, d0.w, r2c);
            if (vd) acc += (double)pair_energy(pB.z, pB.w, c1.w, d1.w, r2d);
        }
    }

    // Odd-pair tail (not hit for 16M pairs; kept for safety).
    if ((nPairs & 1) && blockIdx.x == 0 && threadIdx.x == 0) {
        const int2* p2 = (const int2*)pairs4;
        const int2 p = p2[nPairs - 1];
        const float4 a = __ldg(&g_pos[p.x]);
        const float4 b = __ldg(&g_pos[p.y]);
        const float r2 = min_image_r2(a, b, Lx, Ly, Lz);
        if (r2 < CUT2)
            acc += (double)pair_energy(p.x, p.y, a.w, b.w, r2);
    }

    // Warp reduce -> shared -> one atomic per block (usually nonzero-skipped).
    #pragma unroll
    for (int o = 16; o > 0; o >>= 1)
        acc += __shfl_xor_sync(0xffffffffu, acc, o);

    __shared__ double s_warp[8];
    const int wid = threadIdx.x >> 5;
    if ((threadIdx.x & 31) == 0) s_warp[wid] = acc;
    __syncthreads();

    if (threadIdx.x == 0) {
        double blk = 0.0;
        #pragma unroll
        for (int w = 0; w < 8; w++) blk += s_warp[w];
        if (blk != 0.0) atomicAdd(&g_acc, blk);
        __threadfence();
        unsigned int t = atomicAdd(&g_done, 1u);
        if (t == gridDim.x - 1) {
            __threadfence();
            out[0] = (float)(*(volatile double*)&g_acc);
        }
    }
}

// ---------------------------------------------------------------------------
// Launch. Inputs: coords, box, charges, sigma, epsilon, pairs.
// ---------------------------------------------------------------------------
extern "C" void kernel_launch(void* const* d_in, const int* in_sizes, int n_in,
                              void* d_out, int out_size)
{
    const float* coords  = (const float*)d_in[0];
    const float* box     = (const float*)d_in[1];
    const float* charges = (const float*)d_in[2];
    const float* sigma   = (const float*)d_in[3];
    const float* epsilon = (const float*)d_in[4];
    const int*   pairs   = (const int*)d_in[5];

    const int n      = in_sizes[0] / 3;      // 100000
    const int nPairs = in_sizes[5] / 2;      // 16000000
    const long long nUnits = nPairs / 2;     // int4 units

    nb_pack_kernel<<<(n + 255) / 256, 256>>>(coords, charges, sigma, epsilon, n);
    nb_pair_kernel<<<2048, 256>>>((const int4*)pairs, nUnits, nPairs, box,
                                  (float*)d_out);
}